// round 13
// baseline (speedup 1.0000x reference)
#include <cuda_runtime.h>
#include <cuda_bf16.h>

// Problem constants
#define N_IN   128
#define N_MID  512
#define N_CAT  130

#define RB     148               // blocks = SMs (co-residency for grid barrier)
#define RT     1024              // threads per block (32 warps)
#define WARPS  32
#define SLOTS  (RB * WARPS)      // 4736 warp-slots
#define PQ     33                // float4 quads per partial row (132 floats)

// Scratch (allocation-free)
__device__ float4       g_partial4[RB * PQ];
__device__ unsigned int g_bar;

// Tiny init: reset barrier counter each launch (keeps replays deterministic)
__global__ void init_kernel() { g_bar = 0u; }

// ---------------------------------------------------------------------------
// ONE persistent kernel:
//   phase 1: weighted reduction of x (forward, grid-strided per warp-slot)
//   grid barrier (all 148 blocks resident)
//   gemv (redundant per block, weights from L2): xpbar -> hbar -> o[128]
//   phase 2: out = x + o, each warp re-reads ITS OWN rows newest-first
//            (reverse k) so reads hit L2; __stcs writes stay evict-first.
// ---------------------------------------------------------------------------
__global__ __launch_bounds__(RT, 1)
void fused_kernel(const float* __restrict__ x,
                  const float* __restrict__ w,
                  const float* __restrict__ p,
                  const float* __restrict__ W_in,
                  const float* __restrict__ W_out,
                  float* __restrict__ out,
                  int B)
{
    const int t    = threadIdx.x;
    const int wid  = t >> 5;          // 0..31
    const int lane = t & 31;
    const int slot = blockIdx.x * WARPS + wid;

    const float4* __restrict__ x4 = reinterpret_cast<const float4*>(x);
    float4*       __restrict__ o4 = reinterpret_cast<float4*>(out);

    __shared__ float s_s[WARPS][N_IN];           // 16 KB
    __shared__ float s_w[WARPS];
    __shared__ __align__(16) float fin[4 * PQ];  // 132

    // ---------------- phase 1: weighted reduction ----------------
    {
        float4 acc = make_float4(0.f, 0.f, 0.f, 0.f);
        float  accw = 0.f;

        #pragma unroll 4
        for (int b = slot; b < B; b += SLOTS) {
            const float  wv = __ldg(&w[b]);                      // warp-uniform
            const float4 xv = __ldg(&x4[(size_t)b * 32 + lane]);
            acc.x = fmaf(wv, xv.x, acc.x);
            acc.y = fmaf(wv, xv.y, acc.y);
            acc.z = fmaf(wv, xv.z, acc.z);
            acc.w = fmaf(wv, xv.w, acc.w);
            if (lane == 0) accw += wv;
        }

        reinterpret_cast<float4*>(s_s[wid])[lane] = acc;
        if (lane == 0) s_w[wid] = accw;
        __syncthreads();

        if (t < N_IN) {
            float v = 0.f;
            #pragma unroll
            for (int g = 0; g < WARPS; g++) v += s_s[g][t];
            fin[t] = v;
        } else if (t == N_IN) {
            float v = 0.f;
            #pragma unroll
            for (int g = 0; g < WARPS; g++) v += s_w[g];
            fin[N_IN] = v;
        } else if (t < 4 * PQ) {
            fin[t] = 0.f;                                        // pad 129..131
        }
        __syncthreads();

        if (t < PQ)
            g_partial4[blockIdx.x * PQ + t] =
                reinterpret_cast<const float4*>(fin)[t];
    }

    // ---------------- grid barrier ----------------
    __threadfence();          // publish g_partial4 (gpu scope)
    __syncthreads();
    if (t == 0) {
        atomicAdd(&g_bar, 1u);
        while (*((volatile unsigned int*)&g_bar) < (unsigned int)RB) { }
        __threadfence();      // acquire: order subsequent partial reads
    }
    __syncthreads();

    // ---------------- gemv (redundant per block, all from L2) ----------------
    __shared__ float tmp[7][4 * PQ];             // 7 x 132
    __shared__ __align__(16) float xp[132];
    __shared__ __align__(16) float hb[N_MID];
    __shared__ __align__(16) float so[N_IN];

    // funnel 148 partial rows -> colsum
    if (t < 7 * 132) {                            // 924 threads
        const int col = t % 132, g = t / 132;
        const float* __restrict__ gp = reinterpret_cast<const float*>(g_partial4);
        float v = 0.f;
        #pragma unroll 4
        for (int r = g; r < RB; r += 7) v += gp[r * 132 + col];
        tmp[g][col] = v;
    }
    __syncthreads();
    if (t < 132) {
        float v = 0.f;
        #pragma unroll
        for (int g = 0; g < 7; g++) v += tmp[g][t];
        tmp[0][t] = v;                            // colsum
    }
    __syncthreads();
    if (t < N_IN) {
        xp[t] = tmp[0][t] / tmp[0][N_IN];
    } else if (t == N_IN) {
        xp[N_IN]     = __ldg(&p[0]);
        xp[N_IN + 1] = __ldg(&p[1]);
        xp[130] = 0.f; xp[131] = 0.f;
    }
    __syncthreads();

    // hbar = relu(W_in @ xpbar): warp-per-row, 16 rows/warp, float2 rows
    {
        const float2* __restrict__ xp2 = reinterpret_cast<const float2*>(xp);
        const float2 x0 = xp2[lane];
        const float2 x1 = xp2[lane + 32];
        #pragma unroll 2
        for (int r = wid; r < N_MID; r += WARPS) {
            const float2* __restrict__ row =
                reinterpret_cast<const float2*>(W_in + (size_t)r * N_CAT);
            const float2 w0 = __ldg(&row[lane]);
            const float2 w1 = __ldg(&row[lane + 32]);
            float a = fmaf(w0.x, x0.x, w0.y * x0.y);
            a = fmaf(w1.x, x1.x, fmaf(w1.y, x1.y, a));
            if (lane == 0) {                      // cols 128,129
                const float2 w2 = __ldg(&row[64]);
                a = fmaf(w2.x, xp[128], fmaf(w2.y, xp[129], a));
            }
            #pragma unroll
            for (int s = 16; s; s >>= 1) a += __shfl_xor_sync(0xFFFFFFFFu, a, s);
            if (lane == 0) hb[r] = fmaxf(a, 0.f);
        }
    }
    __syncthreads();

    // o = W_out @ hbar: warp-per-row, 4 rows/warp, float4 rows
    {
        const float4* __restrict__ hb4 = reinterpret_cast<const float4*>(hb);
        const float4 h0 = hb4[lane];
        const float4 h1 = hb4[lane + 32];
        const float4 h2 = hb4[lane + 64];
        const float4 h3 = hb4[lane + 96];
        #pragma unroll
        for (int r = wid; r < N_IN; r += WARPS) {
            const float4* __restrict__ row =
                reinterpret_cast<const float4*>(W_out + (size_t)r * N_MID);
            const float4 w0 = __ldg(&row[lane]);
            const float4 w1 = __ldg(&row[lane + 32]);
            const float4 w2 = __ldg(&row[lane + 64]);
            const float4 w3 = __ldg(&row[lane + 96]);
            float a = fmaf(w0.x, h0.x, w0.y * h0.y);
            a = fmaf(w0.z, h0.z, fmaf(w0.w, h0.w, a));
            a = fmaf(w1.x, h1.x, fmaf(w1.y, h1.y, a));
            a = fmaf(w1.z, h1.z, fmaf(w1.w, h1.w, a));
            a = fmaf(w2.x, h2.x, fmaf(w2.y, h2.y, a));
            a = fmaf(w2.z, h2.z, fmaf(w2.w, h2.w, a));
            a = fmaf(w3.x, h3.x, fmaf(w3.y, h3.y, a));
            a = fmaf(w3.z, h3.z, fmaf(w3.w, h3.w, a));
            #pragma unroll
            for (int s = 16; s; s >>= 1) a += __shfl_xor_sync(0xFFFFFFFFu, a, s);
            if (lane == 0) so[r] = a;
        }
    }
    __syncthreads();

    // ---------------- phase 2: out = x + o (reverse over own rows) ----------
    {
        const float4 ov = reinterpret_cast<const float4*>(so)[lane];
        if (slot < B) {
            const int kmax = (B - 1 - slot) / SLOTS + 1;  // rows for this slot
            #pragma unroll 4
            for (int k = kmax - 1; k >= 0; --k) {
                const size_t b = (size_t)slot + (size_t)k * SLOTS;
                float4 xv = __ldg(&x4[b * 32 + lane]);
                xv.x += ov.x; xv.y += ov.y; xv.z += ov.z; xv.w += ov.w;
                __stcs(&o4[b * 32 + lane], xv);           // evict-first store
            }
        }
    }
}

// ---------------------------------------------------------------------------
extern "C" void kernel_launch(void* const* d_in, const int* in_sizes, int n_in,
                              void* d_out, int out_size)
{
    const float* x     = (const float*)d_in[0];  // [B, 128]
    const float* w     = (const float*)d_in[1];  // [B, 1]
    const float* p     = (const float*)d_in[2];  // [1, 2]
    const float* W_in  = (const float*)d_in[3];  // [512, 130]
    const float* W_out = (const float*)d_in[4];  // [128, 512]
    float* out = (float*)d_out;

    const int B = in_sizes[0] / N_IN;

    init_kernel<<<1, 1>>>();
    fused_kernel<<<RB, RT>>>(x, w, p, W_in, W_out, out, B);
}

// round 14
// speedup vs baseline: 1.0038x; 1.0038x over previous
#include <cuda_runtime.h>
#include <cuda_bf16.h>

// Problem constants
#define N_IN   128
#define N_MID  512
#define N_CAT  130

#define RB     148               // blocks = SMs (co-residency for grid barrier)
#define RT     1024              // threads per block (32 warps)
#define WARPS  32
#define SLOTS  (RB * WARPS)      // 4736 warp-slots
#define PQ     33                // float4 quads per partial row (132 floats)

// Scratch (allocation-free)
__device__ float4       g_partial4[RB * PQ];
__device__ unsigned int g_bar;

// Tiny init: reset barrier counter each launch (keeps replays deterministic)
__global__ void init_kernel() { g_bar = 0u; }

// ---------------------------------------------------------------------------
// ONE persistent kernel:
//   phase 1: weighted reduction of x (forward, grid-strided per warp-slot)
//   grid barrier (all 148 blocks resident)
//   gemv (redundant per block, weights from L2): xpbar -> hbar -> o[128]
//   phase 2: out = x + o, each warp re-reads ITS OWN rows newest-first
//            (reverse k) so reads hit L2; __stcs writes stay evict-first.
// ---------------------------------------------------------------------------
__global__ __launch_bounds__(RT, 1)
void fused_kernel(const float* __restrict__ x,
                  const float* __restrict__ w,
                  const float* __restrict__ p,
                  const float* __restrict__ W_in,
                  const float* __restrict__ W_out,
                  float* __restrict__ out,
                  int B)
{
    const int t    = threadIdx.x;
    const int wid  = t >> 5;          // 0..31
    const int lane = t & 31;
    const int slot = blockIdx.x * WARPS + wid;

    const float4* __restrict__ x4 = reinterpret_cast<const float4*>(x);
    float4*       __restrict__ o4 = reinterpret_cast<float4*>(out);

    __shared__ float s_s[WARPS][N_IN];           // 16 KB
    __shared__ float s_w[WARPS];
    __shared__ __align__(16) float fin[4 * PQ];  // 132

    // ---------------- phase 1: weighted reduction ----------------
    {
        float4 acc = make_float4(0.f, 0.f, 0.f, 0.f);
        float  accw = 0.f;

        #pragma unroll 4
        for (int b = slot; b < B; b += SLOTS) {
            const float  wv = __ldg(&w[b]);                      // warp-uniform
            const float4 xv = __ldg(&x4[(size_t)b * 32 + lane]);
            acc.x = fmaf(wv, xv.x, acc.x);
            acc.y = fmaf(wv, xv.y, acc.y);
            acc.z = fmaf(wv, xv.z, acc.z);
            acc.w = fmaf(wv, xv.w, acc.w);
            if (lane == 0) accw += wv;
        }

        reinterpret_cast<float4*>(s_s[wid])[lane] = acc;
        if (lane == 0) s_w[wid] = accw;
        __syncthreads();

        if (t < N_IN) {
            float v = 0.f;
            #pragma unroll
            for (int g = 0; g < WARPS; g++) v += s_s[g][t];
            fin[t] = v;
        } else if (t == N_IN) {
            float v = 0.f;
            #pragma unroll
            for (int g = 0; g < WARPS; g++) v += s_w[g];
            fin[N_IN] = v;
        } else if (t < 4 * PQ) {
            fin[t] = 0.f;                                        // pad 129..131
        }
        __syncthreads();

        if (t < PQ)
            g_partial4[blockIdx.x * PQ + t] =
                reinterpret_cast<const float4*>(fin)[t];
    }

    // ---------------- grid barrier ----------------
    __threadfence();          // publish g_partial4 (gpu scope)
    __syncthreads();
    if (t == 0) {
        atomicAdd(&g_bar, 1u);
        while (*((volatile unsigned int*)&g_bar) < (unsigned int)RB) { }
        __threadfence();      // acquire: order subsequent partial reads
    }
    __syncthreads();

    // ---------------- gemv (redundant per block, all from L2) ----------------
    __shared__ float tmp[7][4 * PQ];             // 7 x 132
    __shared__ __align__(16) float xp[132];
    __shared__ __align__(16) float hb[N_MID];
    __shared__ __align__(16) float so[N_IN];

    // funnel 148 partial rows -> colsum
    if (t < 7 * 132) {                            // 924 threads
        const int col = t % 132, g = t / 132;
        const float* __restrict__ gp = reinterpret_cast<const float*>(g_partial4);
        float v = 0.f;
        #pragma unroll 4
        for (int r = g; r < RB; r += 7) v += gp[r * 132 + col];
        tmp[g][col] = v;
    }
    __syncthreads();
    if (t < 132) {
        float v = 0.f;
        #pragma unroll
        for (int g = 0; g < 7; g++) v += tmp[g][t];
        tmp[0][t] = v;                            // colsum
    }
    __syncthreads();
    if (t < N_IN) {
        xp[t] = tmp[0][t] / tmp[0][N_IN];
    } else if (t == N_IN) {
        xp[N_IN]     = __ldg(&p[0]);
        xp[N_IN + 1] = __ldg(&p[1]);
        xp[130] = 0.f; xp[131] = 0.f;
    }
    __syncthreads();

    // hbar = relu(W_in @ xpbar): warp-per-row, 16 rows/warp, float2 rows
    {
        const float2* __restrict__ xp2 = reinterpret_cast<const float2*>(xp);
        const float2 x0 = xp2[lane];
        const float2 x1 = xp2[lane + 32];
        #pragma unroll 2
        for (int r = wid; r < N_MID; r += WARPS) {
            const float2* __restrict__ row =
                reinterpret_cast<const float2*>(W_in + (size_t)r * N_CAT);
            const float2 w0 = __ldg(&row[lane]);
            const float2 w1 = __ldg(&row[lane + 32]);
            float a = fmaf(w0.x, x0.x, w0.y * x0.y);
            a = fmaf(w1.x, x1.x, fmaf(w1.y, x1.y, a));
            if (lane == 0) {                      // cols 128,129
                const float2 w2 = __ldg(&row[64]);
                a = fmaf(w2.x, xp[128], fmaf(w2.y, xp[129], a));
            }
            #pragma unroll
            for (int s = 16; s; s >>= 1) a += __shfl_xor_sync(0xFFFFFFFFu, a, s);
            if (lane == 0) hb[r] = fmaxf(a, 0.f);
        }
    }
    __syncthreads();

    // o = W_out @ hbar: warp-per-row, 4 rows/warp, float4 rows
    {
        const float4* __restrict__ hb4 = reinterpret_cast<const float4*>(hb);
        const float4 h0 = hb4[lane];
        const float4 h1 = hb4[lane + 32];
        const float4 h2 = hb4[lane + 64];
        const float4 h3 = hb4[lane + 96];
        #pragma unroll
        for (int r = wid; r < N_IN; r += WARPS) {
            const float4* __restrict__ row =
                reinterpret_cast<const float4*>(W_out + (size_t)r * N_MID);
            const float4 w0 = __ldg(&row[lane]);
            const float4 w1 = __ldg(&row[lane + 32]);
            const float4 w2 = __ldg(&row[lane + 64]);
            const float4 w3 = __ldg(&row[lane + 96]);
            float a = fmaf(w0.x, h0.x, w0.y * h0.y);
            a = fmaf(w0.z, h0.z, fmaf(w0.w, h0.w, a));
            a = fmaf(w1.x, h1.x, fmaf(w1.y, h1.y, a));
            a = fmaf(w1.z, h1.z, fmaf(w1.w, h1.w, a));
            a = fmaf(w2.x, h2.x, fmaf(w2.y, h2.y, a));
            a = fmaf(w2.z, h2.z, fmaf(w2.w, h2.w, a));
            a = fmaf(w3.x, h3.x, fmaf(w3.y, h3.y, a));
            a = fmaf(w3.z, h3.z, fmaf(w3.w, h3.w, a));
            #pragma unroll
            for (int s = 16; s; s >>= 1) a += __shfl_xor_sync(0xFFFFFFFFu, a, s);
            if (lane == 0) so[r] = a;
        }
    }
    __syncthreads();

    // ---------------- phase 2: out = x + o (reverse over own rows) ----------
    {
        const float4 ov = reinterpret_cast<const float4*>(so)[lane];
        if (slot < B) {
            const int kmax = (B - 1 - slot) / SLOTS + 1;  // rows for this slot
            #pragma unroll 4
            for (int k = kmax - 1; k >= 0; --k) {
                const size_t b = (size_t)slot + (size_t)k * SLOTS;
                float4 xv = __ldg(&x4[b * 32 + lane]);
                xv.x += ov.x; xv.y += ov.y; xv.z += ov.z; xv.w += ov.w;
                __stcs(&o4[b * 32 + lane], xv);           // evict-first store
            }
        }
    }
}

// ---------------------------------------------------------------------------
extern "C" void kernel_launch(void* const* d_in, const int* in_sizes, int n_in,
                              void* d_out, int out_size)
{
    const float* x     = (const float*)d_in[0];  // [B, 128]
    const float* w     = (const float*)d_in[1];  // [B, 1]
    const float* p     = (const float*)d_in[2];  // [1, 2]
    const float* W_in  = (const float*)d_in[3];  // [512, 130]
    const float* W_out = (const float*)d_in[4];  // [128, 512]
    float* out = (float*)d_out;

    const int B = in_sizes[0] / N_IN;

    init_kernel<<<1, 1>>>();
    fused_kernel<<<RB, RT>>>(x, w, p, W_in, W_out, out, B);
}